// round 14
// baseline (speedup 1.0000x reference)
#include <cuda_runtime.h>
#include <cuda_bf16.h>

#define B_BATCH 8192
#define N_SUP   64
#define D_DIM   256
#define EPS     1e-8f

#define WARPS_PER_CTA 8
#define ROWS_PER_WARP 2
#define GRID_CTAS     (B_BATCH / (WARPS_PER_CTA * ROWS_PER_WARP))   // 512

#define ROW_F4 (D_DIM / 4)            // 64 float4 per support row
#define BAT_F4 (N_SUP * ROW_F4)       // 4096 float4 per batch row

__device__ float g_dist[B_BATCH];
__device__ unsigned int g_counter = 0;

// One warp handles 2 ADJACENT batch rows with a single interleaved load
// stream: one base pointer, immediate offsets, 4 predicate streams -> up to
// 8 independent LDG.128 per unrolled step and no inter-row pipeline bubble.
__global__ __launch_bounds__(256, 4) void proto_loss_kernel(
    const float* __restrict__ query,     // (B, D)
    const float* __restrict__ support,   // (B, N, D)
    const int*   __restrict__ labels,    // (B, N)
    float* __restrict__ out)             // scalar
{
    const int tid  = threadIdx.x;
    const int lane = tid & 31;
    const int wid  = tid >> 5;
    const int gw   = blockIdx.x * WARPS_PER_CTA + wid;   // 0..4095
    const int bA   = 2 * gw;                             // first batch row
    const int c0   = 2 * lane;                           // lane's float4 col

    const float4* __restrict__ sup4 = reinterpret_cast<const float4*>(
        support + (size_t)bA * N_SUP * D_DIM);           // base of row A; row B = +BAT_F4

    // All 4 ballots up front (labels for rows bA, bA+1 are 128 contiguous ints)
    const int lbase = bA * N_SUP;
    const unsigned mA0 = __ballot_sync(0xFFFFFFFFu, labels[lbase + lane]      == 1);
    const unsigned mA1 = __ballot_sync(0xFFFFFFFFu, labels[lbase + 32 + lane] == 1);
    const unsigned mB0 = __ballot_sync(0xFFFFFFFFu, labels[lbase + 64 + lane] == 1);
    const unsigned mB1 = __ballot_sync(0xFFFFFFFFu, labels[lbase + 96 + lane] == 1);
    const int cntA = __popc(mA0) + __popc(mA1);
    const int cntB = __popc(mB0) + __popc(mB1);

    // Interleaved fully-unrolled predicated accumulation over both rows.
    // Lane owns dims [8*lane, 8*lane+8) as two float4; an enabled support
    // row is a 1KB fully-coalesced warp read. __ldcs: streaming.
    float4 a0 = make_float4(0.f, 0.f, 0.f, 0.f);
    float4 a1 = make_float4(0.f, 0.f, 0.f, 0.f);
    float4 e0 = make_float4(0.f, 0.f, 0.f, 0.f);
    float4 e1 = make_float4(0.f, 0.f, 0.f, 0.f);

    #pragma unroll
    for (int n = 0; n < 32; n++) {
        if ((mA0 >> n) & 1u) {
            float4 v0 = __ldcs(&sup4[n * ROW_F4 + c0]);
            float4 v1 = __ldcs(&sup4[n * ROW_F4 + c0 + 1]);
            a0.x += v0.x; a0.y += v0.y; a0.z += v0.z; a0.w += v0.w;
            a1.x += v1.x; a1.y += v1.y; a1.z += v1.z; a1.w += v1.w;
        }
        if ((mA1 >> n) & 1u) {
            float4 v0 = __ldcs(&sup4[(n + 32) * ROW_F4 + c0]);
            float4 v1 = __ldcs(&sup4[(n + 32) * ROW_F4 + c0 + 1]);
            a0.x += v0.x; a0.y += v0.y; a0.z += v0.z; a0.w += v0.w;
            a1.x += v1.x; a1.y += v1.y; a1.z += v1.z; a1.w += v1.w;
        }
        if ((mB0 >> n) & 1u) {
            float4 v0 = __ldcs(&sup4[BAT_F4 + n * ROW_F4 + c0]);
            float4 v1 = __ldcs(&sup4[BAT_F4 + n * ROW_F4 + c0 + 1]);
            e0.x += v0.x; e0.y += v0.y; e0.z += v0.z; e0.w += v0.w;
            e1.x += v1.x; e1.y += v1.y; e1.z += v1.z; e1.w += v1.w;
        }
        if ((mB1 >> n) & 1u) {
            float4 v0 = __ldcs(&sup4[BAT_F4 + (n + 32) * ROW_F4 + c0]);
            float4 v1 = __ldcs(&sup4[BAT_F4 + (n + 32) * ROW_F4 + c0 + 1]);
            e0.x += v0.x; e0.y += v0.y; e0.z += v0.z; e0.w += v0.w;
            e1.x += v1.x; e1.y += v1.y; e1.z += v1.z; e1.w += v1.w;
        }
    }

    // Prototypes (count==0 fallback to support[b,0,:])
    float4 pA0, pA1, pB0, pB1;
    if (cntA > 0) {
        const float inv = 1.0f / (float)cntA;
        pA0 = make_float4(a0.x * inv, a0.y * inv, a0.z * inv, a0.w * inv);
        pA1 = make_float4(a1.x * inv, a1.y * inv, a1.z * inv, a1.w * inv);
    } else {
        pA0 = sup4[c0];
        pA1 = sup4[c0 + 1];
    }
    if (cntB > 0) {
        const float inv = 1.0f / (float)cntB;
        pB0 = make_float4(e0.x * inv, e0.y * inv, e0.z * inv, e0.w * inv);
        pB1 = make_float4(e1.x * inv, e1.y * inv, e1.z * inv, e1.w * inv);
    } else {
        pB0 = sup4[BAT_F4 + c0];
        pB1 = sup4[BAT_F4 + c0 + 1];
    }

    // Query rows bA, bA+1 (adjacent): one base, immediate offsets
    const float4* __restrict__ qry4 = reinterpret_cast<const float4*>(
        query + (size_t)bA * D_DIM);
    const float4 qA0 = qry4[c0];
    const float4 qA1 = qry4[c0 + 1];
    const float4 qB0 = qry4[ROW_F4 + c0];
    const float4 qB1 = qry4[ROW_F4 + c0 + 1];

    float dA, dB;
    {
        float dx = qA0.x - pA0.x, dy = qA0.y - pA0.y, dz = qA0.z - pA0.z, dw = qA0.w - pA0.w;
        dA = dx * dx + dy * dy + dz * dz + dw * dw;
        dx = qA1.x - pA1.x; dy = qA1.y - pA1.y; dz = qA1.z - pA1.z; dw = qA1.w - pA1.w;
        dA += dx * dx + dy * dy + dz * dz + dw * dw;

        dx = qB0.x - pB0.x; dy = qB0.y - pB0.y; dz = qB0.z - pB0.z; dw = qB0.w - pB0.w;
        dB = dx * dx + dy * dy + dz * dz + dw * dw;
        dx = qB1.x - pB1.x; dy = qB1.y - pB1.y; dz = qB1.z - pB1.z; dw = qB1.w - pB1.w;
        dB += dx * dx + dy * dy + dz * dz + dw * dw;
    }
    #pragma unroll
    for (int off = 16; off > 0; off >>= 1) {
        dA += __shfl_xor_sync(0xFFFFFFFFu, dA, off);
        dB += __shfl_xor_sync(0xFFFFFFFFu, dB, off);
    }

    if (lane == 0) {
        g_dist[bA]     = sqrtf(dA + EPS);
        g_dist[bA + 1] = sqrtf(dB + EPS);
    }

    // ---- last-CTA mean reduce (deterministic fixed-order sum) ----
    __threadfence();
    __syncthreads();
    __shared__ int s_last;
    __shared__ float s_red[WARPS_PER_CTA];
    if (tid == 0)
        s_last = (atomicAdd(&g_counter, 1u) == (unsigned)(GRID_CTAS - 1));
    __syncthreads();

    if (s_last) {
        float s = 0.f;
        #pragma unroll
        for (int i = 0; i < B_BATCH / 256; i++)
            s += g_dist[tid + i * 256];

        #pragma unroll
        for (int off = 16; off > 0; off >>= 1)
            s += __shfl_xor_sync(0xFFFFFFFFu, s, off);
        if (lane == 0) s_red[wid] = s;
        __syncthreads();
        if (tid < WARPS_PER_CTA) {
            float w = s_red[tid];
            #pragma unroll
            for (int off = WARPS_PER_CTA / 2; off > 0; off >>= 1)
                w += __shfl_xor_sync(0xFFu, w, off);
            if (tid == 0) {
                out[0] = w * (1.0f / (float)B_BATCH);
                g_counter = 0;   // reset for next graph replay
            }
        }
    }
}

extern "C" void kernel_launch(void* const* d_in, const int* in_sizes, int n_in,
                              void* d_out, int out_size)
{
    const float* query   = (const float*)d_in[0];
    const float* support = (const float*)d_in[1];
    const int*   labels  = (const int*)d_in[2];
    float* out = (float*)d_out;

    proto_loss_kernel<<<GRID_CTAS, 256>>>(query, support, labels, out);
}